// round 8
// baseline (speedup 1.0000x reference)
#include <cuda_runtime.h>
#include <cstdint>

#define NTH 512
#define VSZ   26944
#define XT_O  0       // 64 x 65
#define RBF_O 4160    // 64 x 68
#define A1_O  8512    // 64 x 132
#define BB_O  16960   // 64 x 136
#define PB_O  25664   // 7 x 128
#define LNB_O 26688   // float2[64][2]
#define WFS_O (2*VSZ)
#define SMF   (2*VSZ + 64)   // 53952 floats = 215808 B

__device__ __forceinline__ void cpa16(uint32_t dst, const void* src){
  asm volatile("cp.async.cg.shared.global [%0], [%1], 16;"::"r"(dst),"l"(src):"memory");
}
#define CPCOMMIT() asm volatile("cp.async.commit_group;":::"memory")
#define CPWAIT0()  asm volatile("cp.async.wait_group 0;":::"memory")
__device__ __forceinline__ void vbar(int id){
  asm volatile("bar.sync %0, 256;"::"r"(id):"memory");
}
__device__ __forceinline__ uint32_t s2u(const void* p){
  uint32_t a;
  asm("{.reg .u64 t; cvta.to.shared.u64 t,%1; cvt.u32.u64 %0,t;}":"=r"(a):"l"(p));
  return a;
}
__device__ __forceinline__ void mma8(float (&d)[4],
                                     uint32_t a0, uint32_t a1, uint32_t a2, uint32_t a3,
                                     uint32_t b0, uint32_t b1){
  asm("mma.sync.aligned.m16n8k8.row.col.f32.tf32.tf32.f32 "
      "{%0,%1,%2,%3},{%4,%5,%6,%7},{%8,%9},{%0,%1,%2,%3};"
      : "+f"(d[0]), "+f"(d[1]), "+f"(d[2]), "+f"(d[3])
      : "r"(a0), "r"(a1), "r"(a2), "r"(a3), "r"(b0), "r"(b1));
}
__device__ __forceinline__ float clampf(float v,float lo,float hi){return fminf(fmaxf(v,lo),hi);}
__device__ __forceinline__ float gelu_f(float x){
  float u = x*(0.7978845608f + 0.035677408f*x*x);
  float t; asm("tanh.approx.f32 %0, %1;":"=f"(t):"f"(u));
  return 0.5f*x*(1.0f+t);
}
__device__ __forceinline__ float softplus_f(float x){return (x>15.0f)?x:log1pf(expf(x));}
__device__ __forceinline__ float quad_sum(float v){
  v += __shfl_xor_sync(0xffffffffu, v, 1);
  v += __shfl_xor_sync(0xffffffffu, v, 2);
  return v;
}

template<int KSTEPS>
__device__ __forceinline__ void gemm_steps(float (&acc)[8][4],
                                           const float* __restrict__ A, int sA, int rA0,
                                           const float* __restrict__ ws, int nbg, int t,
                                           int kA0)
{
#pragma unroll 4
  for(int ks=0; ks<KSTEPS; ++ks){
    const int k = ks*8;
    const float* ar0 = A + rA0*sA + kA0 + k + t;
    const float* ar1 = ar0 + 8*sA;
    uint32_t a0 = __float_as_uint(ar0[0]);
    uint32_t a2 = __float_as_uint(ar0[4]);
    uint32_t a1 = __float_as_uint(ar1[0]);
    uint32_t a3 = __float_as_uint(ar1[4]);
    const float* wp0 = ws + (k+t)*136 + nbg;
    const float* wp1 = wp0 + 4*136;
#pragma unroll
    for(int j=0;j<8;++j){
      uint32_t b0 = __float_as_uint(wp0[j*8]);
      uint32_t b1 = __float_as_uint(wp1[j*8]);
      mma8(acc[j], a0, a1, a2, a3, b0, b1);
    }
  }
}

// stage W[64][128] row-major -> bb[64][136] via cp.async (256 threads)
__device__ __forceinline__ void stage64(uint32_t bbu, const float* __restrict__ W, int vtid){
  int n4 = (vtid & 31) << 2;
  int k0 = vtid >> 5;
#pragma unroll
  for(int i=0;i<8;++i){
    int k = k0 + i*8;
    cpa16(bbu + (uint32_t)(k*136 + n4)*4u, W + k*128 + n4);
  }
}

__global__ void __launch_bounds__(NTH, 1)
nam_v2_kernel(const float* __restrict__ x,const float* __restrict__ centers,
              const float* __restrict__ logw,
              const float* __restrict__ W1,const float* __restrict__ b1,
              const float* __restrict__ g1,const float* __restrict__ be1,
              const float* __restrict__ W2,const float* __restrict__ b2,
              const float* __restrict__ g2,const float* __restrict__ be2,
              const float* __restrict__ Wr,const float* __restrict__ br,
              const float* __restrict__ att,const float* __restrict__ bias,
              const float* __restrict__ Wpi,const float* __restrict__ bpi,
              const float* __restrict__ Wa,const float* __restrict__ ba,
              const float* __restrict__ Wb,const float* __restrict__ bb_,
              float* __restrict__ out)
{
  extern __shared__ float sm[];
  const int tid = threadIdx.x;
  const int vcta = tid >> 8;
  const int vtid = tid & 255;
  const int bar_id = vcta + 1;

  float* base = sm + vcta*VSZ;
  float* xt  = base + XT_O;
  float* rbf = base + RBF_O;
  float* a1s = base + A1_O;
  float* bbf = base + BB_O;
  float* pbf = base + PB_O;
  float2* lnb = (float2*)(base + LNB_O);
  float* hb  = base + PB_O;         // reused after feature loop
  float* wfs = sm + WFS_O;
  const uint32_t bbu = s2u(bbf);

  const int w = vtid >> 5, lane = vtid & 31;
  const int g = lane >> 2, t = lane & 3;
  const int wr = w >> 1, wc = w & 1;
  const int rA0 = wr*16 + g;          // rows rA0, rA0+8 in 0..63
  const int nbg = wc*64 + g;
  const int vbase = blockIdx.x*128 + vcta*64;

  // one-time: x tile (clamped) + softmax(att)
#pragma unroll
  for(int i=0;i<16;++i){
    int id = vtid + i*256;
    int r = id >> 6, ff = id & 63;
    xt[r*65 + ff] = clampf(x[(vbase + r)*64 + ff], -10.f, 10.f);
  }
  if(tid == 0){
    float mx = -3.4e38f;
    for(int i=0;i<64;++i) mx = fmaxf(mx, att[i]);
    float s = 0.f;
    for(int i=0;i<64;++i){ float e = expf(att[i]-mx); wfs[i] = e; s += e; }
    float inv = 1.f/s;
    for(int i=0;i<64;++i) wfs[i] *= inv;
  }
  __syncthreads();

  float agg[2][16];
#pragma unroll
  for(int r2=0;r2<2;++r2)
#pragma unroll
    for(int j=0;j<16;++j) agg[r2][j] = 0.f;

  for(int f=0; f<64; ++f){
    vbar(bar_id);                        // S0: bb free (prev GEMMr done)
    stage64(bbu, W1 + (size_t)f*8192, vtid); CPCOMMIT();

    // RBF -> rbf (xt in smem), params -> pb  (overlaps W1 copy)
#pragma unroll
    for(int i=0;i<4;++i){
      int id = vtid + i*256;
      int row = id >> 4, n4 = (id & 15) << 2;
      float xv = xt[row*65 + f];
      float4 ce = *(const float4*)&centers[f*64 + n4];
      float4 lw = *(const float4*)&logw[f*64 + n4];
      float4 o;
      { float wd=__expf(clampf(lw.x,-5.f,5.f))+0.1f; float d=clampf(__fdividef(xv-ce.x,wd),-10.f,10.f); o.x=__expf(-0.5f*d*d); }
      { float wd=__expf(clampf(lw.y,-5.f,5.f))+0.1f; float d=clampf(__fdividef(xv-ce.y,wd),-10.f,10.f); o.y=__expf(-0.5f*d*d); }
      { float wd=__expf(clampf(lw.z,-5.f,5.f))+0.1f; float d=clampf(__fdividef(xv-ce.z,wd),-10.f,10.f); o.z=__expf(-0.5f*d*d); }
      { float wd=__expf(clampf(lw.w,-5.f,5.f))+0.1f; float d=clampf(__fdividef(xv-ce.w,wd),-10.f,10.f); o.w=__expf(-0.5f*d*d); }
      *(float4*)&rbf[row*68 + n4] = o;
    }
    for(int i=vtid; i<896; i+=256){
      int seg = i >> 7, c = i & 127;
      const float* sp = (seg==0)?b1:(seg==1)?g1:(seg==2)?be1:(seg==3)?b2:(seg==4)?g2:(seg==5)?be2:br;
      pbf[i] = sp[f*128 + c];
    }
    CPWAIT0();
    vbar(bar_id);                        // S1: bb=W1; rbf/pb visible

    // GEMM1 + LN1 stats
    float acc[8][4];
#pragma unroll
    for(int j=0;j<8;++j){ acc[j][0]=acc[j][1]=acc[j][2]=acc[j][3]=0.f; }
    gemm_steps<8>(acc, rbf, 68, rA0, bbf, nbg, t, 0);
    {
      float s0=0.f,q0=0.f,s1=0.f,q1=0.f;
#pragma unroll
      for(int j=0;j<8;++j){
        int col = wc*64 + j*8 + t*2;
        float2 bv = *(const float2*)&pbf[col];
        float v0=acc[j][0]+bv.x, v1=acc[j][1]+bv.y;
        float v2=acc[j][2]+bv.x, v3=acc[j][3]+bv.y;
        s0+=v0+v1; q0+=v0*v0+v1*v1;
        s1+=v2+v3; q1+=v2*v2+v3*v3;
      }
      s0=quad_sum(s0); q0=quad_sum(q0); s1=quad_sum(s1); q1=quad_sum(q1);
      if(t==0){
        lnb[rA0*2 + wc]     = make_float2(s0,q0);
        lnb[(rA0+8)*2 + wc] = make_float2(s1,q1);
      }
    }
    vbar(bar_id);                        // S2: GEMM1 reads done; lnb visible
    stage64(bbu, W2 + (size_t)f*16384, vtid); CPCOMMIT();

    // epilogue 1 -> a1  (overlaps W2a copy)
    {
      float2 pA0 = lnb[rA0*2 + wc],     pB0 = lnb[rA0*2 + (wc^1)];
      float2 pA1 = lnb[(rA0+8)*2 + wc], pB1 = lnb[(rA0+8)*2 + (wc^1)];
      float mu0=(pA0.x+pB0.x)*(1.f/128.f);
      float rs0=rsqrtf((pA0.y+pB0.y)*(1.f/128.f)-mu0*mu0+1e-5f);
      float mu1=(pA1.x+pB1.x)*(1.f/128.f);
      float rs1=rsqrtf((pA1.y+pB1.y)*(1.f/128.f)-mu1*mu1+1e-5f);
#pragma unroll
      for(int j=0;j<8;++j){
        int col = wc*64 + j*8 + t*2;
        float2 bv = *(const float2*)&pbf[col];
        float2 gv = *(const float2*)&pbf[128+col];
        float2 ev = *(const float2*)&pbf[256+col];
        float v0 = gelu_f((acc[j][0]+bv.x-mu0)*rs0*gv.x+ev.x);
        float v1 = gelu_f((acc[j][1]+bv.y-mu0)*rs0*gv.y+ev.y);
        float v2 = gelu_f((acc[j][2]+bv.x-mu1)*rs1*gv.x+ev.x);
        float v3 = gelu_f((acc[j][3]+bv.y-mu1)*rs1*gv.y+ev.y);
        *(float2*)&a1s[rA0*132 + col]     = make_float2(v0,v1);
        *(float2*)&a1s[(rA0+8)*132 + col] = make_float2(v2,v3);
      }
    }
    CPWAIT0();
    vbar(bar_id);                        // S3: bb=W2a; a1 visible

    float acc2[8][4];
#pragma unroll
    for(int j=0;j<8;++j){ acc2[j][0]=acc2[j][1]=acc2[j][2]=acc2[j][3]=0.f; }
    gemm_steps<8>(acc2, a1s, 132, rA0, bbf, nbg, t, 0);   // GEMM2a
    vbar(bar_id);                        // S4: reads done
    stage64(bbu, W2 + (size_t)f*16384 + 8192, vtid); CPCOMMIT(); CPWAIT0();
    vbar(bar_id);                        // S5: bb=W2b
    gemm_steps<8>(acc2, a1s, 132, rA0, bbf, nbg, t, 64);  // GEMM2b
    {
      float s0=0.f,q0=0.f,s1=0.f,q1=0.f;
#pragma unroll
      for(int j=0;j<8;++j){
        int col = wc*64 + j*8 + t*2;
        float2 bv = *(const float2*)&pbf[384+col];
        float v0=acc2[j][0]+bv.x, v1=acc2[j][1]+bv.y;
        float v2=acc2[j][2]+bv.x, v3=acc2[j][3]+bv.y;
        s0+=v0+v1; q0+=v0*v0+v1*v1;
        s1+=v2+v3; q1+=v2*v2+v3*v3;
      }
      s0=quad_sum(s0); q0=quad_sum(q0); s1=quad_sum(s1); q1=quad_sum(q1);
      if(t==0){
        lnb[rA0*2 + wc]     = make_float2(s0,q0);
        lnb[(rA0+8)*2 + wc] = make_float2(s1,q1);
      }
    }
    vbar(bar_id);                        // S6: GEMM2b reads done; lnb visible
    stage64(bbu, Wr + (size_t)f*8192, vtid); CPCOMMIT();

    // epilogue 2 -> agg  (overlaps Wr copy)
    const float wf = wfs[f];
    {
      float2 pA0 = lnb[rA0*2 + wc],     pB0 = lnb[rA0*2 + (wc^1)];
      float2 pA1 = lnb[(rA0+8)*2 + wc], pB1 = lnb[(rA0+8)*2 + (wc^1)];
      float mu0=(pA0.x+pB0.x)*(1.f/128.f);
      float rs0=rsqrtf((pA0.y+pB0.y)*(1.f/128.f)-mu0*mu0+1e-5f);
      float mu1=(pA1.x+pB1.x)*(1.f/128.f);
      float rs1=rsqrtf((pA1.y+pB1.y)*(1.f/128.f)-mu1*mu1+1e-5f);
#pragma unroll
      for(int j=0;j<8;++j){
        int col = wc*64 + j*8 + t*2;
        float2 bv = *(const float2*)&pbf[384+col];
        float2 gv = *(const float2*)&pbf[512+col];
        float2 ev = *(const float2*)&pbf[640+col];
        agg[0][j*2]   += wf*gelu_f((acc2[j][0]+bv.x-mu0)*rs0*gv.x+ev.x);
        agg[0][j*2+1] += wf*gelu_f((acc2[j][1]+bv.y-mu0)*rs0*gv.y+ev.y);
        agg[1][j*2]   += wf*gelu_f((acc2[j][2]+bv.x-mu1)*rs1*gv.x+ev.x);
        agg[1][j*2+1] += wf*gelu_f((acc2[j][3]+bv.y-mu1)*rs1*gv.y+ev.y);
      }
    }
    CPWAIT0();
    vbar(bar_id);                        // S7: bb=Wr
    float accr[8][4];
#pragma unroll
    for(int j=0;j<8;++j){ accr[j][0]=accr[j][1]=accr[j][2]=accr[j][3]=0.f; }
    gemm_steps<8>(accr, rbf, 68, rA0, bbf, nbg, t, 0);    // GEMMr
    {
      const float cr = 0.1f*wf;
#pragma unroll
      for(int j=0;j<8;++j){
        int col = wc*64 + j*8 + t*2;
        float2 bv = *(const float2*)&pbf[768+col];
        agg[0][j*2]   += cr*(accr[j][0]+bv.x);
        agg[0][j*2+1] += cr*(accr[j][1]+bv.y);
        agg[1][j*2]   += cr*(accr[j][2]+bv.x);
        agg[1][j*2+1] += cr*(accr[j][3]+bv.y);
      }
    }
  }

  // ---- mixture-beta head (per vCTA) ----
  float p[2][9];
#pragma unroll
  for(int r2=0;r2<2;++r2)
#pragma unroll
    for(int q=0;q<9;++q) p[r2][q]=0.f;
#pragma unroll
  for(int j=0;j<8;++j){
#pragma unroll
    for(int cc=0;cc<2;++cc){
      int c = wc*64 + j*8 + t*2 + cc;
      float bs = __ldg(&bias[c]);
      float av0 = agg[0][j*2+cc] + bs;
      float av1 = agg[1][j*2+cc] + bs;
#pragma unroll
      for(int q=0;q<3;++q){
        float wp=__ldg(&Wpi[c*3+q]);
        float wa=__ldg(&Wa[c*3+q]);
        float wb=__ldg(&Wb[c*3+q]);
        p[0][q]+=av0*wp;   p[1][q]+=av1*wp;
        p[0][3+q]+=av0*wa; p[1][3+q]+=av1*wa;
        p[0][6+q]+=av0*wb; p[1][6+q]+=av1*wb;
      }
    }
  }
#pragma unroll
  for(int r2=0;r2<2;++r2)
#pragma unroll
    for(int q=0;q<9;++q) p[r2][q]=quad_sum(p[r2][q]);

  vbar(bar_id);                          // pb/lnb region free -> hb
  if(t==0){
#pragma unroll
    for(int q=0;q<9;++q){
      hb[(wc*64 + rA0)*9 + q]     = p[0][q];
      hb[(wc*64 + rA0 + 8)*9 + q] = p[1][q];
    }
  }
  vbar(bar_id);

  if(wc==0 && t==0){
#pragma unroll
    for(int rr=0;rr<2;++rr){
      int r = rA0 + rr*8;
      float z[9];
#pragma unroll
      for(int q=0;q<9;++q) z[q] = hb[r*9+q] + hb[(64+r)*9+q];
      float p0=z[0]+bpi[0], p1=z[1]+bpi[1], p2=z[2]+bpi[2];
      float m=fmaxf(p0,fmaxf(p1,p2));
      float e0=expf(p0-m), e1=expf(p1-m), e2=expf(p2-m);
      float al0=clampf(softplus_f(z[3]+ba[0])+1.01f,1.01f,100.f);
      float al1=clampf(softplus_f(z[4]+ba[1])+1.01f,1.01f,100.f);
      float al2=clampf(softplus_f(z[5]+ba[2])+1.01f,1.01f,100.f);
      float bt0=clampf(softplus_f(z[6]+bb_[0])+1.01f,1.01f,100.f);
      float bt1=clampf(softplus_f(z[7]+bb_[1])+1.01f,1.01f,100.f);
      float bt2=clampf(softplus_f(z[8]+bb_[2])+1.01f,1.01f,100.f);
      float pred=e0*al0/(al0+bt0)+e1*al1/(al1+bt1)+e2*al2/(al2+bt2);
      pred/=(e0+e1+e2);
      out[vbase+r]=clampf(pred,0.001f,0.999f);
    }
  }
}

extern "C" void kernel_launch(void* const* d_in,const int* in_sizes,int n_in,
                              void* d_out,int out_size)
{
  const float* x=(const float*)d_in[0];
  const float* centers=(const float*)d_in[1];
  const float* logw=(const float*)d_in[2];
  const float* W1=(const float*)d_in[3];
  const float* b1=(const float*)d_in[4];
  const float* g1=(const float*)d_in[5];
  const float* be1=(const float*)d_in[6];
  const float* W2=(const float*)d_in[7];
  const float* b2=(const float*)d_in[8];
  const float* g2=(const float*)d_in[9];
  const float* be2=(const float*)d_in[10];
  const float* Wr=(const float*)d_in[11];
  const float* br=(const float*)d_in[12];
  const float* att=(const float*)d_in[13];
  const float* bias=(const float*)d_in[14];
  const float* Wpi=(const float*)d_in[15];
  const float* bpi=(const float*)d_in[16];
  const float* Wa=(const float*)d_in[17];
  const float* ba=(const float*)d_in[18];
  const float* Wb=(const float*)d_in[19];
  const float* bb=(const float*)d_in[20];
  float* out=(float*)d_out;

  const int smem_bytes = SMF*4;   // 215808 B
  cudaFuncSetAttribute(nam_v2_kernel,cudaFuncAttributeMaxDynamicSharedMemorySize,smem_bytes);
  nam_v2_kernel<<<128,NTH,smem_bytes>>>(x,centers,logw,W1,b1,g1,be1,W2,b2,g2,be2,
                                        Wr,br,att,bias,Wpi,bpi,Wa,ba,Wb,bb,out);
}

// round 10
// speedup vs baseline: 1.0053x; 1.0053x over previous
#include <cuda_runtime.h>
#include <cstdint>

#define NTH 256
#define XT_O  0       // 64 x 65
#define RBF_O 4160    // 64 x 68
#define A1_O  8512    // 64 x 132
#define BB_O  16960   // 64 x 136
#define PB_O  25664   // 7 x 128 (reused as hb: 128*9 after loop)
#define LNB_O 26688   // float2[64][2]
#define WFS_O 26944
#define SMF   27008   // floats -> 108032 B

__device__ __forceinline__ void cpa16(uint32_t dst, const void* src){
  asm volatile("cp.async.cg.shared.global [%0], [%1], 16;"::"r"(dst),"l"(src):"memory");
}
#define CPCOMMIT() asm volatile("cp.async.commit_group;":::"memory")
#define CPWAIT0()  asm volatile("cp.async.wait_group 0;":::"memory")
__device__ __forceinline__ uint32_t s2u(const void* p){
  uint32_t a;
  asm("{.reg .u64 t; cvta.to.shared.u64 t,%1; cvt.u32.u64 %0,t;}":"=r"(a):"l"(p));
  return a;
}
__device__ __forceinline__ void mma8(float (&d)[4],
                                     uint32_t a0, uint32_t a1, uint32_t a2, uint32_t a3,
                                     uint32_t b0, uint32_t b1){
  asm("mma.sync.aligned.m16n8k8.row.col.f32.tf32.tf32.f32 "
      "{%0,%1,%2,%3},{%4,%5,%6,%7},{%8,%9},{%0,%1,%2,%3};"
      : "+f"(d[0]), "+f"(d[1]), "+f"(d[2]), "+f"(d[3])
      : "r"(a0), "r"(a1), "r"(a2), "r"(a3), "r"(b0), "r"(b1));
}
__device__ __forceinline__ float clampf(float v,float lo,float hi){return fminf(fmaxf(v,lo),hi);}
__device__ __forceinline__ float gelu_f(float x){
  float u = x*(0.7978845608f + 0.035677408f*x*x);
  float t; asm("tanh.approx.f32 %0, %1;":"=f"(t):"f"(u));
  return 0.5f*x*(1.0f+t);
}
__device__ __forceinline__ float softplus_f(float x){return (x>15.0f)?x:log1pf(expf(x));}
__device__ __forceinline__ float quad_sum(float v){
  v += __shfl_xor_sync(0xffffffffu, v, 1);
  v += __shfl_xor_sync(0xffffffffu, v, 2);
  return v;
}

template<int KSTEPS>
__device__ __forceinline__ void gemm_steps(float (&acc)[8][4],
                                           const float* __restrict__ A, int sA, int rA0,
                                           const float* __restrict__ ws, int nbg, int t,
                                           int kA0)
{
#pragma unroll 4
  for(int ks=0; ks<KSTEPS; ++ks){
    const int k = ks*8;
    const float* ar0 = A + rA0*sA + kA0 + k + t;
    const float* ar1 = ar0 + 8*sA;
    uint32_t a0 = __float_as_uint(ar0[0]);
    uint32_t a2 = __float_as_uint(ar0[4]);
    uint32_t a1 = __float_as_uint(ar1[0]);
    uint32_t a3 = __float_as_uint(ar1[4]);
    const float* wp0 = ws + (k+t)*136 + nbg;
    const float* wp1 = wp0 + 4*136;
#pragma unroll
    for(int j=0;j<8;++j){
      uint32_t b0 = __float_as_uint(wp0[j*8]);
      uint32_t b1 = __float_as_uint(wp1[j*8]);
      mma8(acc[j], a0, a1, a2, a3, b0, b1);
    }
  }
}

// stage W[64][128] row-major -> bb[64][136] via cp.async (256 threads)
__device__ __forceinline__ void stage64(uint32_t bbu, const float* __restrict__ W, int tid){
  int n4 = (tid & 31) << 2;
  int k0 = tid >> 5;
#pragma unroll
  for(int i=0;i<8;++i){
    int k = k0 + i*8;
    cpa16(bbu + (uint32_t)(k*136 + n4)*4u, W + k*128 + n4);
  }
}

__global__ void __launch_bounds__(NTH, 2)
nam_2cta_kernel(const float* __restrict__ x,const float* __restrict__ centers,
                const float* __restrict__ logw,
                const float* __restrict__ W1,const float* __restrict__ b1,
                const float* __restrict__ g1,const float* __restrict__ be1,
                const float* __restrict__ W2,const float* __restrict__ b2,
                const float* __restrict__ g2,const float* __restrict__ be2,
                const float* __restrict__ Wr,const float* __restrict__ br,
                const float* __restrict__ att,const float* __restrict__ bias,
                const float* __restrict__ Wpi,const float* __restrict__ bpi,
                const float* __restrict__ Wa,const float* __restrict__ ba,
                const float* __restrict__ Wb,const float* __restrict__ bb_,
                float* __restrict__ out)
{
  extern __shared__ float sm[];
  float* xt  = sm + XT_O;
  float* rbf = sm + RBF_O;
  float* a1s = sm + A1_O;
  float* bbf = sm + BB_O;
  float* pbf = sm + PB_O;
  float2* lnb = (float2*)(sm + LNB_O);
  float* hb  = sm + PB_O;            // reused after feature loop (1152 fl fits before WFS)
  float* wfs = sm + WFS_O;
  const uint32_t bbu = s2u(bbf);

  const int tid = threadIdx.x;
  const int w = tid >> 5, lane = tid & 31;
  const int g = lane >> 2, t = lane & 3;
  const int wr = w >> 1, wc = w & 1;
  const int rA0 = wr*16 + g;          // rows rA0, rA0+8 in 0..63
  const int nbg = wc*64 + g;
  const int vbase = blockIdx.x * 64;

  // one-time: x tile (clamped) + softmax(att)
#pragma unroll
  for(int i=0;i<16;++i){
    int id = tid + i*256;
    int r = id >> 6, ff = id & 63;
    xt[r*65 + ff] = clampf(x[(vbase + r)*64 + ff], -10.f, 10.f);
  }
  if(tid == 0){
    float mx = -3.4e38f;
    for(int i=0;i<64;++i) mx = fmaxf(mx, att[i]);
    float s = 0.f;
    for(int i=0;i<64;++i){ float e = expf(att[i]-mx); wfs[i] = e; s += e; }
    float inv = 1.f/s;
    for(int i=0;i<64;++i) wfs[i] *= inv;
  }
  __syncthreads();

  float agg[2][16];
#pragma unroll
  for(int r2=0;r2<2;++r2)
#pragma unroll
    for(int j=0;j<16;++j) agg[r2][j] = 0.f;

  for(int f=0; f<64; ++f){
    __syncthreads();                     // S0: bb free (prev GEMMr done)
    stage64(bbu, W1 + (size_t)f*8192, tid); CPCOMMIT();

    // RBF -> rbf (xt in smem), params -> pb  (overlaps W1 copy)
#pragma unroll
    for(int i=0;i<4;++i){
      int id = tid + i*256;
      int row = id >> 4, n4 = (id & 15) << 2;
      float xv = xt[row*65 + f];
      float4 ce = *(const float4*)&centers[f*64 + n4];
      float4 lw = *(const float4*)&logw[f*64 + n4];
      float4 o;
      { float wd=__expf(clampf(lw.x,-5.f,5.f))+0.1f; float d=clampf(__fdividef(xv-ce.x,wd),-10.f,10.f); o.x=__expf(-0.5f*d*d); }
      { float wd=__expf(clampf(lw.y,-5.f,5.f))+0.1f; float d=clampf(__fdividef(xv-ce.y,wd),-10.f,10.f); o.y=__expf(-0.5f*d*d); }
      { float wd=__expf(clampf(lw.z,-5.f,5.f))+0.1f; float d=clampf(__fdividef(xv-ce.z,wd),-10.f,10.f); o.z=__expf(-0.5f*d*d); }
      { float wd=__expf(clampf(lw.w,-5.f,5.f))+0.1f; float d=clampf(__fdividef(xv-ce.w,wd),-10.f,10.f); o.w=__expf(-0.5f*d*d); }
      *(float4*)&rbf[row*68 + n4] = o;
    }
    for(int i=tid; i<896; i+=256){
      int seg = i >> 7, c = i & 127;
      const float* sp = (seg==0)?b1:(seg==1)?g1:(seg==2)?be1:(seg==3)?b2:(seg==4)?g2:(seg==5)?be2:br;
      pbf[i] = sp[f*128 + c];
    }
    CPWAIT0();
    __syncthreads();                     // S1: bb=W1; rbf/pb visible

    // GEMM1 + LN1 stats
    float acc[8][4];
#pragma unroll
    for(int j=0;j<8;++j){ acc[j][0]=acc[j][1]=acc[j][2]=acc[j][3]=0.f; }
    gemm_steps<8>(acc, rbf, 68, rA0, bbf, nbg, t, 0);
    {
      float s0=0.f,q0=0.f,s1=0.f,q1=0.f;
#pragma unroll
      for(int j=0;j<8;++j){
        int col = wc*64 + j*8 + t*2;
        float2 bv = *(const float2*)&pbf[col];
        float v0=acc[j][0]+bv.x, v1=acc[j][1]+bv.y;
        float v2=acc[j][2]+bv.x, v3=acc[j][3]+bv.y;
        s0+=v0+v1; q0+=v0*v0+v1*v1;
        s1+=v2+v3; q1+=v2*v2+v3*v3;
      }
      s0=quad_sum(s0); q0=quad_sum(q0); s1=quad_sum(s1); q1=quad_sum(q1);
      if(t==0){
        lnb[rA0*2 + wc]     = make_float2(s0,q0);
        lnb[(rA0+8)*2 + wc] = make_float2(s1,q1);
      }
    }
    __syncthreads();                     // S2: GEMM1 reads done; lnb visible
    stage64(bbu, W2 + (size_t)f*16384, tid); CPCOMMIT();

    // epilogue 1 -> a1  (overlaps W2a copy)
    {
      float2 pA0 = lnb[rA0*2 + wc],     pB0 = lnb[rA0*2 + (wc^1)];
      float2 pA1 = lnb[(rA0+8)*2 + wc], pB1 = lnb[(rA0+8)*2 + (wc^1)];
      float mu0=(pA0.x+pB0.x)*(1.f/128.f);
      float rs0=rsqrtf((pA0.y+pB0.y)*(1.f/128.f)-mu0*mu0+1e-5f);
      float mu1=(pA1.x+pB1.x)*(1.f/128.f);
      float rs1=rsqrtf((pA1.y+pB1.y)*(1.f/128.f)-mu1*mu1+1e-5f);
#pragma unroll
      for(int j=0;j<8;++j){
        int col = wc*64 + j*8 + t*2;
        float2 bv = *(const float2*)&pbf[col];
        float2 gv = *(const float2*)&pbf[128+col];
        float2 ev = *(const float2*)&pbf[256+col];
        float v0 = gelu_f((acc[j][0]+bv.x-mu0)*rs0*gv.x+ev.x);
        float v1 = gelu_f((acc[j][1]+bv.y-mu0)*rs0*gv.y+ev.y);
        float v2 = gelu_f((acc[j][2]+bv.x-mu1)*rs1*gv.x+ev.x);
        float v3 = gelu_f((acc[j][3]+bv.y-mu1)*rs1*gv.y+ev.y);
        *(float2*)&a1s[rA0*132 + col]     = make_float2(v0,v1);
        *(float2*)&a1s[(rA0+8)*132 + col] = make_float2(v2,v3);
      }
    }
    CPWAIT0();
    __syncthreads();                     // S3: bb=W2a; a1 visible

    float acc2[8][4];
#pragma unroll
    for(int j=0;j<8;++j){ acc2[j][0]=acc2[j][1]=acc2[j][2]=acc2[j][3]=0.f; }
    gemm_steps<8>(acc2, a1s, 132, rA0, bbf, nbg, t, 0);   // GEMM2a
    __syncthreads();                     // S4: reads done
    stage64(bbu, W2 + (size_t)f*16384 + 8192, tid); CPCOMMIT(); CPWAIT0();
    __syncthreads();                     // S5: bb=W2b (sibling CTA covers this wait)
    gemm_steps<8>(acc2, a1s, 132, rA0, bbf, nbg, t, 64);  // GEMM2b
    {
      float s0=0.f,q0=0.f,s1=0.f,q1=0.f;
#pragma unroll
      for(int j=0;j<8;++j){
        int col = wc*64 + j*8 + t*2;
        float2 bv = *(const float2*)&pbf[384+col];
        float v0=acc2[j][0]+bv.x, v1=acc2[j][1]+bv.y;
        float v2=acc2[j][2]+bv.x, v3=acc2[j][3]+bv.y;
        s0+=v0+v1; q0+=v0*v0+v1*v1;
        s1+=v2+v3; q1+=v2*v2+v3*v3;
      }
      s0=quad_sum(s0); q0=quad_sum(q0); s1=quad_sum(s1); q1=quad_sum(q1);
      if(t==0){
        lnb[rA0*2 + wc]     = make_float2(s0,q0);
        lnb[(rA0+8)*2 + wc] = make_float2(s1,q1);
      }
    }
    __syncthreads();                     // S6: GEMM2b reads done; lnb visible
    stage64(bbu, Wr + (size_t)f*8192, tid); CPCOMMIT();

    // epilogue 2 -> agg  (overlaps Wr copy)
    const float wf = wfs[f];
    {
      float2 pA0 = lnb[rA0*2 + wc],     pB0 = lnb[rA0*2 + (wc^1)];
      float2 pA1 = lnb[(rA0+8)*2 + wc], pB1 = lnb[(rA0+8)*2 + (wc^1)];
      float mu0=(pA0.x+pB0.x)*(1.f/128.f);
      float rs0=rsqrtf((pA0.y+pB0.y)*(1.f/128.f)-mu0*mu0+1e-5f);
      float mu1=(pA1.x+pB1.x)*(1.f/128.f);
      float rs1=rsqrtf((pA1.y+pB1.y)*(1.f/128.f)-mu1*mu1+1e-5f);
#pragma unroll
      for(int j=0;j<8;++j){
        int col = wc*64 + j*8 + t*2;
        float2 bv = *(const float2*)&pbf[384+col];
        float2 gv = *(const float2*)&pbf[512+col];
        float2 ev = *(const float2*)&pbf[640+col];
        agg[0][j*2]   += wf*gelu_f((acc2[j][0]+bv.x-mu0)*rs0*gv.x+ev.x);
        agg[0][j*2+1] += wf*gelu_f((acc2[j][1]+bv.y-mu0)*rs0*gv.y+ev.y);
        agg[1][j*2]   += wf*gelu_f((acc2[j][2]+bv.x-mu1)*rs1*gv.x+ev.x);
        agg[1][j*2+1] += wf*gelu_f((acc2[j][3]+bv.y-mu1)*rs1*gv.y+ev.y);
      }
    }
    CPWAIT0();
    __syncthreads();                     // S7: bb=Wr
    float accr[8][4];
#pragma unroll
    for(int j=0;j<8;++j){ accr[j][0]=accr[j][1]=accr[j][2]=accr[j][3]=0.f; }
    gemm_steps<8>(accr, rbf, 68, rA0, bbf, nbg, t, 0);    // GEMMr
    {
      const float cr = 0.1f*wf;
#pragma unroll
      for(int j=0;j<8;++j){
        int col = wc*64 + j*8 + t*2;
        float2 bv = *(const float2*)&pbf[768+col];
        agg[0][j*2]   += cr*(accr[j][0]+bv.x);
        agg[0][j*2+1] += cr*(accr[j][1]+bv.y);
        agg[1][j*2]   += cr*(accr[j][2]+bv.x);
        agg[1][j*2+1] += cr*(accr[j][3]+bv.y);
      }
    }
  }

  // ---- mixture-beta head ----
  float p[2][9];
#pragma unroll
  for(int r2=0;r2<2;++r2)
#pragma unroll
    for(int q=0;q<9;++q) p[r2][q]=0.f;
#pragma unroll
  for(int j=0;j<8;++j){
#pragma unroll
    for(int cc=0;cc<2;++cc){
      int c = wc*64 + j*8 + t*2 + cc;
      float bs = __ldg(&bias[c]);
      float av0 = agg[0][j*2+cc] + bs;
      float av1 = agg[1][j*2+cc] + bs;
#pragma unroll
      for(int q=0;q<3;++q){
        float wp=__ldg(&Wpi[c*3+q]);
        float wa=__ldg(&Wa[c*3+q]);
        float wb=__ldg(&Wb[c*3+q]);
        p[0][q]+=av0*wp;   p[1][q]+=av1*wp;
        p[0][3+q]+=av0*wa; p[1][3+q]+=av1*wa;
        p[0][6+q]+=av0*wb; p[1][6+q]+=av1*wb;
      }
    }
  }
#pragma unroll
  for(int r2=0;r2<2;++r2)
#pragma unroll
    for(int q=0;q<9;++q) p[r2][q]=quad_sum(p[r2][q]);

  __syncthreads();                       // pb/lnb region free -> hb
  if(t==0){
#pragma unroll
    for(int q=0;q<9;++q){
      hb[(wc*64 + rA0)*9 + q]     = p[0][q];
      hb[(wc*64 + rA0 + 8)*9 + q] = p[1][q];
    }
  }
  __syncthreads();

  if(wc==0 && t==0){
#pragma unroll
    for(int rr=0;rr<2;++rr){
      int r = rA0 + rr*8;
      float z[9];
#pragma unroll
      for(int q=0;q<9;++q) z[q] = hb[r*9+q] + hb[(64+r)*9+q];
      float p0=z[0]+bpi[0], p1=z[1]+bpi[1], p2=z[2]+bpi[2];
      float m=fmaxf(p0,fmaxf(p1,p2));
      float e0=expf(p0-m), e1=expf(p1-m), e2=expf(p2-m);
      float al0=clampf(softplus_f(z[3]+ba[0])+1.01f,1.01f,100.f);
      float al1=clampf(softplus_f(z[4]+ba[1])+1.01f,1.01f,100.f);
      float al2=clampf(softplus_f(z[5]+ba[2])+1.01f,1.01f,100.f);
      float bt0=clampf(softplus_f(z[6]+bb_[0])+1.01f,1.01f,100.f);
      float bt1=clampf(softplus_f(z[7]+bb_[1])+1.01f,1.01f,100.f);
      float bt2=clampf(softplus_f(z[8]+bb_[2])+1.01f,1.01f,100.f);
      float pred=e0*al0/(al0+bt0)+e1*al1/(al1+bt1)+e2*al2/(al2+bt2);
      pred/=(e0+e1+e2);
      out[vbase+r]=clampf(pred,0.001f,0.999f);
    }
  }
}

extern "C" void kernel_launch(void* const* d_in,const int* in_sizes,int n_in,
                              void* d_out,int out_size)
{
  const float* x=(const float*)d_in[0];
  const float* centers=(const float*)d_in[1];
  const float* logw=(const float*)d_in[2];
  const float* W1=(const float*)d_in[3];
  const float* b1=(const float*)d_in[4];
  const float* g1=(const float*)d_in[5];
  const float* be1=(const float*)d_in[6];
  const float* W2=(const float*)d_in[7];
  const float* b2=(const float*)d_in[8];
  const float* g2=(const float*)d_in[9];
  const float* be2=(const float*)d_in[10];
  const float* Wr=(const float*)d_in[11];
  const float* br=(const float*)d_in[12];
  const float* att=(const float*)d_in[13];
  const float* bias=(const float*)d_in[14];
  const float* Wpi=(const float*)d_in[15];
  const float* bpi=(const float*)d_in[16];
  const float* Wa=(const float*)d_in[17];
  const float* ba=(const float*)d_in[18];
  const float* Wb=(const float*)d_in[19];
  const float* bb=(const float*)d_in[20];
  float* out=(float*)d_out;

  const int smem_bytes = SMF*4;   // 108032 B -> 2 CTAs/SM
  cudaFuncSetAttribute(nam_2cta_kernel,cudaFuncAttributeMaxDynamicSharedMemorySize,smem_bytes);
  nam_2cta_kernel<<<256,NTH,smem_bytes>>>(x,centers,logw,W1,b1,g1,be1,W2,b2,g2,be2,
                                          Wr,br,att,bias,Wpi,bpi,Wa,ba,Wb,bb,out);
}

// round 15
// speedup vs baseline: 1.5098x; 1.5018x over previous
#include <cuda_runtime.h>
#include <cuda_fp16.h>
#include <cstdint>

#define NTH 256
// smem byte offsets
#define XT_B   0        // f32 64x65
#define RBF_B  16640    // f16 64x72  (144B rows)
#define A1_B   25856    // f16 64x136 (272B rows)
#define BB_B   43264    // f16 weight tile, up to 128x136 (272B rows) = 34816B
#define PB_B   78080    // f32 7x128
#define LNB_B  81664    // float2[64][2]
#define WFS_B  82688    // f32 64
#define SMEM_B 82944

#define NUNITS 1048576          // 2M halfs as uint32 units (4MB)
__device__ unsigned int g_wt[NUNITS];

__device__ __forceinline__ void cpa16(uint32_t dst, const void* src){
  asm volatile("cp.async.cg.shared.global [%0], [%1], 16;"::"r"(dst),"l"(src):"memory");
}
#define CPCOMMIT() asm volatile("cp.async.commit_group;":::"memory")
#define CPWAIT0()  asm volatile("cp.async.wait_group 0;":::"memory")
__device__ __forceinline__ uint32_t s2u(const void* p){
  uint32_t a;
  asm("{.reg .u64 t; cvta.to.shared.u64 t,%1; cvt.u32.u64 %0,t;}":"=r"(a):"l"(p));
  return a;
}
__device__ __forceinline__ void ldsm4(uint32_t&r0,uint32_t&r1,uint32_t&r2,uint32_t&r3,uint32_t a){
  asm volatile("ldmatrix.sync.aligned.m8n8.x4.shared.b16 {%0,%1,%2,%3}, [%4];"
               :"=r"(r0),"=r"(r1),"=r"(r2),"=r"(r3):"r"(a));
}
__device__ __forceinline__ void mma16(float (&d)[4],
                                      uint32_t a0,uint32_t a1,uint32_t a2,uint32_t a3,
                                      uint32_t b0,uint32_t b1){
  asm("mma.sync.aligned.m16n8k16.row.col.f32.f16.f16.f32 "
      "{%0,%1,%2,%3},{%4,%5,%6,%7},{%8,%9},{%0,%1,%2,%3};"
      : "+f"(d[0]),"+f"(d[1]),"+f"(d[2]),"+f"(d[3])
      : "r"(a0),"r"(a1),"r"(a2),"r"(a3),"r"(b0),"r"(b1));
}
__device__ __forceinline__ uint32_t pkh(float a, float b){
  __half2 h = __floats2half2_rn(a,b);
  return *(uint32_t*)&h;
}
__device__ __forceinline__ float clampf(float v,float lo,float hi){return fminf(fmaxf(v,lo),hi);}
__device__ __forceinline__ float gelu_f(float x){
  float u = x*(0.7978845608f + 0.035677408f*x*x);
  float t; asm("tanh.approx.f32 %0, %1;":"=f"(t):"f"(u));
  return 0.5f*x*(1.0f+t);
}
__device__ __forceinline__ float softplus_f(float x){return (x>15.0f)?x:log1pf(expf(x));}
__device__ __forceinline__ float quad_sum(float v){
  v += __shfl_xor_sync(0xffffffffu, v, 1);
  v += __shfl_xor_sync(0xffffffffu, v, 2);
  return v;
}

// KS k16-steps; aaddr/baddr = per-lane ldmatrix base addresses; bstride = B row bytes
template<int KS>
__device__ __forceinline__ void gemm_h(float (&acc)[8][4], uint32_t aaddr,
                                       uint32_t baddr, int bstride)
{
  uint32_t bp0 = baddr;
  uint32_t bp1 = baddr + 16*bstride;
  uint32_t bp2 = baddr + 32*bstride;
  uint32_t bp3 = baddr + 48*bstride;
#pragma unroll
  for(int ks=0; ks<KS; ++ks){
    uint32_t a0,a1,a2,a3;
    ldsm4(a0,a1,a2,a3, aaddr); aaddr += 32;
    uint32_t b0,b1,b2,b3;
    ldsm4(b0,b1,b2,b3, bp0); bp0 += 32;
    mma16(acc[0], a0,a1,a2,a3, b0,b1);
    mma16(acc[1], a0,a1,a2,a3, b2,b3);
    ldsm4(b0,b1,b2,b3, bp1); bp1 += 32;
    mma16(acc[2], a0,a1,a2,a3, b0,b1);
    mma16(acc[3], a0,a1,a2,a3, b2,b3);
    ldsm4(b0,b1,b2,b3, bp2); bp2 += 32;
    mma16(acc[4], a0,a1,a2,a3, b0,b1);
    mma16(acc[5], a0,a1,a2,a3, b2,b3);
    ldsm4(b0,b1,b2,b3, bp3); bp3 += 32;
    mma16(acc[6], a0,a1,a2,a3, b0,b1);
    mma16(acc[7], a0,a1,a2,a3, b2,b3);
  }
}

// ---- prep kernel: W(f32,[k][n]) -> g_wt(f16,[f][n][k] half2-packed) ----
__global__ void prep_kernel(const float* __restrict__ W1,
                            const float* __restrict__ W2,
                            const float* __restrict__ Wr)
{
  for(int u = blockIdx.x*blockDim.x + threadIdx.x; u < NUNITS; u += gridDim.x*blockDim.x){
    float v0, v1;
    if(u < 262144){                       // W1: K=64
      int f = u >> 12, rem = u & 4095;
      int n = rem >> 5, kp = rem & 31;
      const float* s = W1 + (size_t)f*8192 + (kp*2)*128 + n;
      v0 = s[0]; v1 = s[128];
    } else if(u < 786432){                // W2: K=128
      int v = u - 262144;
      int f = v >> 13, rem = v & 8191;
      int n = rem >> 6, kp = rem & 63;
      const float* s = W2 + (size_t)f*16384 + (kp*2)*128 + n;
      v0 = s[0]; v1 = s[128];
    } else {                              // Wr: K=64
      int v = u - 786432;
      int f = v >> 12, rem = v & 4095;
      int n = rem >> 5, kp = rem & 31;
      const float* s = Wr + (size_t)f*8192 + (kp*2)*128 + n;
      v0 = s[0]; v1 = s[128];
    }
    g_wt[u] = pkh(v0, v1);
  }
}

__global__ void __launch_bounds__(NTH, 2)
nam_h_kernel(const float* __restrict__ x,const float* __restrict__ centers,
             const float* __restrict__ logw,
             const float* __restrict__ b1,const float* __restrict__ g1,
             const float* __restrict__ be1,const float* __restrict__ b2,
             const float* __restrict__ g2,const float* __restrict__ be2,
             const float* __restrict__ br,
             const float* __restrict__ att,const float* __restrict__ bias,
             const float* __restrict__ Wpi,const float* __restrict__ bpi,
             const float* __restrict__ Wa,const float* __restrict__ ba,
             const float* __restrict__ Wb,const float* __restrict__ bb_,
             float* __restrict__ out)
{
  extern __shared__ char smc[];
  float* xt  = (float*)(smc + XT_B);
  float* pbf = (float*)(smc + PB_B);
  float2* lnb = (float2*)(smc + LNB_B);
  float* wfs = (float*)(smc + WFS_B);
  float* hb  = (float*)(smc + PB_B);      // reused after loop (4608B = PB+LNB)
  const uint32_t smu = s2u(smc);
  const __half* gw = (const __half*)g_wt;

  const int tid = threadIdx.x;
  const int w = tid >> 5, lane = tid & 31;
  const int g = lane >> 2, t = lane & 3;
  const int wr = w >> 1, wc = w & 1;
  const int rA0 = wr*16 + g;
  const int vbase = blockIdx.x * 64;

  // per-lane ldmatrix addresses
  const int arow = wr*16 + (lane&7) + ((lane>>3)&1)*8;
  const int akoff = (lane>>4)*16;
  const uint32_t aaddr_rbf = smu + RBF_B + arow*144 + akoff;
  const uint32_t aaddr_a1  = smu + A1_B  + arow*272 + akoff;
  const int brow = wc*64 + (lane>>4)*8 + (lane&7);
  const int bkoff = ((lane>>3)&1)*16;
  const uint32_t baddr64  = smu + BB_B + brow*144 + bkoff;
  const uint32_t baddr128 = smu + BB_B + brow*272 + bkoff;

  // one-time: x tile + softmax(att)
#pragma unroll
  for(int i=0;i<16;++i){
    int id = tid + i*256;
    int r = id >> 6, ff = id & 63;
    xt[r*65 + ff] = clampf(x[(vbase + r)*64 + ff], -10.f, 10.f);
  }
  if(tid == 0){
    float mx = -3.4e38f;
    for(int i=0;i<64;++i) mx = fmaxf(mx, att[i]);
    float s = 0.f;
    for(int i=0;i<64;++i){ float e = expf(att[i]-mx); wfs[i] = e; s += e; }
    float inv = 1.f/s;
    for(int i=0;i<64;++i) wfs[i] *= inv;
  }
  __syncthreads();

  float agg[2][16];
#pragma unroll
  for(int r2=0;r2<2;++r2)
#pragma unroll
    for(int j=0;j<16;++j) agg[r2][j] = 0.f;

  for(int f=0; f<64; ++f){
    __syncthreads();                       // S0: bb free (prev GEMMr done)
    // stage W1t (f16, [n64? n128][k64]) -> bb (144B rows)
    {
      const __half* src = gw + (size_t)f*8192;
#pragma unroll
      for(int i=0;i<4;++i){
        int id = tid + i*256;
        int n = id >> 3, c = id & 7;
        cpa16(smu + BB_B + (uint32_t)(n*144 + c*16), src + n*64 + c*8);
      }
      CPCOMMIT();
    }
    // RBF -> rbf_h (f16), params -> pb
#pragma unroll
    for(int i=0;i<4;++i){
      int id = tid + i*256;
      int row = id >> 4, k4 = (id & 15) << 2;
      float xv = xt[row*65 + f];
      float4 ce = *(const float4*)&centers[f*64 + k4];
      float4 lw = *(const float4*)&logw[f*64 + k4];
      float o0,o1,o2,o3;
      { float wd=__expf(clampf(lw.x,-5.f,5.f))+0.1f; float d=clampf(__fdividef(xv-ce.x,wd),-10.f,10.f); o0=__expf(-0.5f*d*d); }
      { float wd=__expf(clampf(lw.y,-5.f,5.f))+0.1f; float d=clampf(__fdividef(xv-ce.y,wd),-10.f,10.f); o1=__expf(-0.5f*d*d); }
      { float wd=__expf(clampf(lw.z,-5.f,5.f))+0.1f; float d=clampf(__fdividef(xv-ce.z,wd),-10.f,10.f); o2=__expf(-0.5f*d*d); }
      { float wd=__expf(clampf(lw.w,-5.f,5.f))+0.1f; float d=clampf(__fdividef(xv-ce.w,wd),-10.f,10.f); o3=__expf(-0.5f*d*d); }
      uint2 u2; u2.x = pkh(o0,o1); u2.y = pkh(o2,o3);
      *(uint2*)(smc + RBF_B + row*144 + k4*2) = u2;
    }
    for(int i=tid; i<896; i+=256){
      int seg = i >> 7, c = i & 127;
      const float* sp = (seg==0)?b1:(seg==1)?g1:(seg==2)?be1:(seg==3)?b2:(seg==4)?g2:(seg==5)?be2:br;
      pbf[i] = sp[f*128 + c];
    }
    CPWAIT0();
    __syncthreads();                       // S1: bb=W1t; rbf/pb visible

    // GEMM1 + LN1 stats
    float acc[8][4];
#pragma unroll
    for(int j=0;j<8;++j){ acc[j][0]=acc[j][1]=acc[j][2]=acc[j][3]=0.f; }
    gemm_h<4>(acc, aaddr_rbf, baddr64, 144);
    {
      float s0=0.f,q0=0.f,s1=0.f,q1=0.f;
#pragma unroll
      for(int j=0;j<8;++j){
        int col = wc*64 + j*8 + t*2;
        float2 bv = *(const float2*)&pbf[col];
        float v0=acc[j][0]+bv.x, v1=acc[j][1]+bv.y;
        float v2=acc[j][2]+bv.x, v3=acc[j][3]+bv.y;
        s0+=v0+v1; q0+=v0*v0+v1*v1;
        s1+=v2+v3; q1+=v2*v2+v3*v3;
      }
      s0=quad_sum(s0); q0=quad_sum(q0); s1=quad_sum(s1); q1=quad_sum(q1);
      if(t==0){
        lnb[rA0*2 + wc]     = make_float2(s0,q0);
        lnb[(rA0+8)*2 + wc] = make_float2(s1,q1);
      }
    }
    __syncthreads();                       // S2: GEMM1 reads done; lnb visible

    // stage W2t (full 128k) -> bb; epi1 -> a1_h
    {
      const __half* src = gw + 524288 + (size_t)f*16384;
#pragma unroll
      for(int i=0;i<8;++i){
        int id = tid + i*256;
        int n = id >> 4, c = id & 15;
        cpa16(smu + BB_B + (uint32_t)(n*272 + c*16), src + n*128 + c*8);
      }
      CPCOMMIT();
    }
    {
      float2 pA0 = lnb[rA0*2 + wc],     pB0 = lnb[rA0*2 + (wc^1)];
      float2 pA1 = lnb[(rA0+8)*2 + wc], pB1 = lnb[(rA0+8)*2 + (wc^1)];
      float mu0=(pA0.x+pB0.x)*(1.f/128.f);
      float rs0=rsqrtf((pA0.y+pB0.y)*(1.f/128.f)-mu0*mu0+1e-5f);
      float mu1=(pA1.x+pB1.x)*(1.f/128.f);
      float rs1=rsqrtf((pA1.y+pB1.y)*(1.f/128.f)-mu1*mu1+1e-5f);
#pragma unroll
      for(int j=0;j<8;++j){
        int col = wc*64 + j*8 + t*2;
        float2 bv = *(const float2*)&pbf[col];
        float2 gv = *(const float2*)&pbf[128+col];
        float2 ev = *(const float2*)&pbf[256+col];
        float v0 = gelu_f((acc[j][0]+bv.x-mu0)*rs0*gv.x+ev.x);
        float v1 = gelu_f((acc[j][1]+bv.y-mu0)*rs0*gv.y+ev.y);
        float v2 = gelu_f((acc[j][2]+bv.x-mu1)*rs1*gv.x+ev.x);
        float v3 = gelu_f((acc[j][3]+bv.y-mu1)*rs1*gv.y+ev.y);
        *(uint32_t*)(smc + A1_B + rA0*272 + col*2)     = pkh(v0,v1);
        *(uint32_t*)(smc + A1_B + (rA0+8)*272 + col*2) = pkh(v2,v3);
      }
    }
    CPWAIT0();
    __syncthreads();                       // S3: bb=W2t; a1 visible

    // GEMM2 (K=128, one shot) + LN2 stats
    float acc2[8][4];
#pragma unroll
    for(int j=0;j<8;++j){ acc2[j][0]=acc2[j][1]=acc2[j][2]=acc2[j][3]=0.f; }
    gemm_h<8>(acc2, aaddr_a1, baddr128, 272);
    {
      float s0=0.f,q0=0.f,s1=0.f,q1=0.f;
#pragma unroll
      for(int j=0;j<8;++j){
        int col = wc*64 + j*8 + t*2;
        float2 bv = *(const float2*)&pbf[384+col];
        float v0=acc2[j][0]+bv.x, v1=acc2[j][1]+bv.y;
        float v2=acc2[j][2]+bv.x, v3=acc2[j][3]+bv.y;
        s0+=v0+v1; q0+=v0*v0+v1*v1;
        s1+=v2+v3; q1+=v2*v2+v3*v3;
      }
      s0=quad_sum(s0); q0=quad_sum(q0); s1=quad_sum(s1); q1=quad_sum(q1);
      if(t==0){
        lnb[rA0*2 + wc]     = make_float2(s0,q0);
        lnb[(rA0+8)*2 + wc] = make_float2(s1,q1);
      }
    }
    __syncthreads();                       // S4: GEMM2 reads done; lnb visible

    // stage Wrt -> bb; epi2 -> agg
    {
      const __half* src = gw + 1572864 + (size_t)f*8192;
#pragma unroll
      for(int i=0;i<4;++i){
        int id = tid + i*256;
        int n = id >> 3, c = id & 7;
        cpa16(smu + BB_B + (uint32_t)(n*144 + c*16), src + n*64 + c*8);
      }
      CPCOMMIT();
    }
    const float wf = wfs[f];
    {
      float2 pA0 = lnb[rA0*2 + wc],     pB0 = lnb[rA0*2 + (wc^1)];
      float2 pA1 = lnb[(rA0+8)*2 + wc], pB1 = lnb[(rA0+8)*2 + (wc^1)];
      float mu0=(pA0.x+pB0.x)*(1.f/128.f);
      float rs0=rsqrtf((pA0.y+pB0.y)*(1.f/128.f)-mu0*mu0+1e-5f);
      float mu1=(pA1.x+pB1.x)*(1.f/128.f);
      float rs1=rsqrtf((pA1.y+pB1.y)*(1.f/128.f)-mu1*mu1+1e-5f);
#pragma unroll
      for(int j=0;j<8;++j){
        int col = wc*64 + j*8 + t*2;
        float2 bv = *(const float2*)&pbf[384+col];
        float2 gv = *(const float2*)&pbf[512+col];
        float2 ev = *(const float2*)&pbf[640+col];
        agg[0][j*2]   += wf*gelu_f((acc2[j][0]+bv.x-mu0)*rs0*gv.x+ev.x);
        agg[0][j*2+1] += wf*gelu_f((acc2[j][1]+bv.y-mu0)*rs0*gv.y+ev.y);
        agg[1][j*2]   += wf*gelu_f((acc2[j][2]+bv.x-mu1)*rs1*gv.x+ev.x);
        agg[1][j*2+1] += wf*gelu_f((acc2[j][3]+bv.y-mu1)*rs1*gv.y+ev.y);
      }
    }
    CPWAIT0();
    __syncthreads();                       // S5: bb=Wrt
    float accr[8][4];
#pragma unroll
    for(int j=0;j<8;++j){ accr[j][0]=accr[j][1]=accr[j][2]=accr[j][3]=0.f; }
    gemm_h<4>(accr, aaddr_rbf, baddr64, 144);
    {
      const float cr = 0.1f*wf;
#pragma unroll
      for(int j=0;j<8;++j){
        int col = wc*64 + j*8 + t*2;
        float2 bv = *(const float2*)&pbf[768+col];
        agg[0][j*2]   += cr*(accr[j][0]+bv.x);
        agg[0][j*2+1] += cr*(accr[j][1]+bv.y);
        agg[1][j*2]   += cr*(accr[j][2]+bv.x);
        agg[1][j*2+1] += cr*(accr[j][3]+bv.y);
      }
    }
  }

  // ---- mixture-beta head ----
  float p[2][9];
#pragma unroll
  for(int r2=0;r2<2;++r2)
#pragma unroll
    for(int q=0;q<9;++q) p[r2][q]=0.f;
#pragma unroll
  for(int j=0;j<8;++j){
#pragma unroll
    for(int cc=0;cc<2;++cc){
      int c = wc*64 + j*8 + t*2 + cc;
      float bs = __ldg(&bias[c]);
      float av0 = agg[0][j*2+cc] + bs;
      float av1 = agg[1][j*2+cc] + bs;
#pragma unroll
      for(int q=0;q<3;++q){
        float wp=__ldg(&Wpi[c*3+q]);
        float wa=__ldg(&Wa[c*3+q]);
        float wb=__ldg(&Wb[c*3+q]);
        p[0][q]+=av0*wp;   p[1][q]+=av1*wp;
        p[0][3+q]+=av0*wa; p[1][3+q]+=av1*wa;
        p[0][6+q]+=av0*wb; p[1][6+q]+=av1*wb;
      }
    }
  }
#pragma unroll
  for(int r2=0;r2<2;++r2)
#pragma unroll
    for(int q=0;q<9;++q) p[r2][q]=quad_sum(p[r2][q]);

  __syncthreads();
  if(t==0){
#pragma unroll
    for(int q=0;q<9;++q){
      hb[(wc*64 + rA0)*9 + q]     = p[0][q];
      hb[(wc*64 + rA0 + 8)*9 + q] = p[1][q];
    }
  }
  __syncthreads();

  if(wc==0 && t==0){
#pragma unroll
    for(int rr=0;rr<2;++rr){
      int r = rA0 + rr*8;
      float z[9];
#pragma unroll
      for(int q=0;q<9;++q) z[q] = hb[r*9+q] + hb[(64+r)*9+q];
      float p0=z[0]+bpi[0], p1=z[1]+bpi[1], p2=z[2]+bpi[2];
      float m=fmaxf(p0,fmaxf(p1,p2));
      float e0=expf(p0-m), e1=expf(p1-m), e2=expf(p2-m);
      float al0=clampf(softplus_f(z[3]+ba[0])+1.01f,1.01f,100.f);
      float al1=clampf(softplus_f(z[4]+ba[1])+1.01f,1.01f,100.f);
      float al2=clampf(softplus_f(z[5]+ba[2])+1.01f,1.01f,100.f);
      float bt0=clampf(softplus_f(z[6]+bb_[0])+1.01f,1.01f,100.f);
      float bt1=clampf(softplus_f(z[7]+bb_[1])+1.01f,1.01f,100.f);
      float bt2=clampf(softplus_f(z[8]+bb_[2])+1.01f,1.01f,100.f);
      float pred=e0*al0/(al0+bt0)+e1*al1/(al1+bt1)+e2*al2/(al2+bt2);
      pred/=(e0+e1+e2);
      out[vbase+r]=clampf(pred,0.001f,0.999f);
    }
  }
}

extern "C" void kernel_launch(void* const* d_in,const int* in_sizes,int n_in,
                              void* d_out,int out_size)
{
  const float* x=(const float*)d_in[0];
  const float* centers=(const float*)d_in[1];
  const float* logw=(const float*)d_in[2];
  const float* W1=(const float*)d_in[3];
  const float* b1=(const float*)d_in[4];
  const float* g1=(const float*)d_in[5];
  const float* be1=(const float*)d_in[6];
  const float* W2=(const float*)d_in[7];
  const float* b2=(const float*)d_in[8];
  const float* g2=(const float*)d_in[9];
  const float* be2=(const float*)d_in[10];
  const float* Wr=(const float*)d_in[11];
  const float* br=(const float*)d_in[12];
  const float* att=(const float*)d_in[13];
  const float* bias=(const float*)d_in[14];
  const float* Wpi=(const float*)d_in[15];
  const float* bpi=(const float*)d_in[16];
  const float* Wa=(const float*)d_in[17];
  const float* ba=(const float*)d_in[18];
  const float* Wb=(const float*)d_in[19];
  const float* bb=(const float*)d_in[20];
  float* out=(float*)d_out;

  prep_kernel<<<512, 256>>>(W1, W2, Wr);

  cudaFuncSetAttribute(nam_h_kernel,cudaFuncAttributeMaxDynamicSharedMemorySize,SMEM_B);
  nam_h_kernel<<<256,NTH,SMEM_B>>>(x,centers,logw,b1,g1,be1,b2,g2,be2,br,
                                   att,bias,Wpi,bpi,Wa,ba,Wb,bb,out);
}

// round 16
// speedup vs baseline: 1.5517x; 1.0277x over previous
#include <cuda_runtime.h>
#include <cuda_fp16.h>
#include <cstdint>

#define NTH 256
// smem byte offsets
#define XT_B   0        // f32 64x65
#define RBF_B  16640    // f16 64 rows x 144B
#define A1_B   25856    // f16 64 rows x 272B
#define BB_B   43264    // weights: W1 at +0 (18432), Wr at +18432 ; or W2 (34816)
#define BBR_OFF 18432
#define PB_B   80128    // f32 7x128
#define LNB_B  83712    // float2[64][2]
#define WFS_B  84736    // f32 64
#define SMEM_B 84992

#define NUNITS 1048576          // 2M halfs as uint32 units (4MB)
__device__ unsigned int g_wt[NUNITS];

__device__ __forceinline__ void cpa16(uint32_t dst, const void* src){
  asm volatile("cp.async.cg.shared.global [%0], [%1], 16;"::"r"(dst),"l"(src):"memory");
}
#define CPCOMMIT() asm volatile("cp.async.commit_group;":::"memory")
#define CPWAIT0()  asm volatile("cp.async.wait_group 0;":::"memory")
__device__ __forceinline__ uint32_t s2u(const void* p){
  uint32_t a;
  asm("{.reg .u64 t; cvta.to.shared.u64 t,%1; cvt.u32.u64 %0,t;}":"=r"(a):"l"(p));
  return a;
}
__device__ __forceinline__ void ldsm4(uint32_t&r0,uint32_t&r1,uint32_t&r2,uint32_t&r3,uint32_t a){
  asm volatile("ldmatrix.sync.aligned.m8n8.x4.shared.b16 {%0,%1,%2,%3}, [%4];"
               :"=r"(r0),"=r"(r1),"=r"(r2),"=r"(r3):"r"(a));
}
__device__ __forceinline__ void mma16(float (&d)[4],
                                      uint32_t a0,uint32_t a1,uint32_t a2,uint32_t a3,
                                      uint32_t b0,uint32_t b1){
  asm("mma.sync.aligned.m16n8k16.row.col.f32.f16.f16.f32 "
      "{%0,%1,%2,%3},{%4,%5,%6,%7},{%8,%9},{%0,%1,%2,%3};"
      : "+f"(d[0]),"+f"(d[1]),"+f"(d[2]),"+f"(d[3])
      : "r"(a0),"r"(a1),"r"(a2),"r"(a3),"r"(b0),"r"(b1));
}
__device__ __forceinline__ uint32_t pkh(float a, float b){
  __half2 h = __floats2half2_rn(a,b);
  return *(uint32_t*)&h;
}
__device__ __forceinline__ uint32_t gelu_h2(uint32_t xp){
  __half2 x = *(__half2*)&xp;
  __half2 x2 = __hmul2(x,x);
  __half2 u = __hmul2(x, __hfma2(x2, __float2half2_rn(0.035677408f),
                                 __float2half2_rn(0.7978845608f)));
  uint32_t uu = *(uint32_t*)&u, tt;
  asm("tanh.approx.f16x2 %0, %1;":"=r"(tt):"r"(uu));
  __half2 t = *(__half2*)&tt;
  __half2 y = __hmul2(__hmul2(x, __float2half2_rn(0.5f)),
                      __hadd2(t, __float2half2_rn(1.f)));
  return *(uint32_t*)&y;
}
__device__ __forceinline__ float clampf(float v,float lo,float hi){return fminf(fmaxf(v,lo),hi);}
__device__ __forceinline__ float gelu_f(float x){
  float u = x*(0.7978845608f + 0.035677408f*x*x);
  float t; asm("tanh.approx.f32 %0, %1;":"=f"(t):"f"(u));
  return 0.5f*x*(1.0f+t);
}
__device__ __forceinline__ float softplus_f(float x){return (x>15.0f)?x:log1pf(expf(x));}
__device__ __forceinline__ float quad_sum(float v){
  v += __shfl_xor_sync(0xffffffffu, v, 1);
  v += __shfl_xor_sync(0xffffffffu, v, 2);
  return v;
}

template<int KS>
__device__ __forceinline__ void gemm_h(float (&acc)[8][4], uint32_t aaddr,
                                       uint32_t baddr, int bstride)
{
  uint32_t bp0 = baddr;
  uint32_t bp1 = baddr + 16*bstride;
  uint32_t bp2 = baddr + 32*bstride;
  uint32_t bp3 = baddr + 48*bstride;
#pragma unroll
  for(int ks=0; ks<KS; ++ks){
    uint32_t a0,a1,a2,a3;
    ldsm4(a0,a1,a2,a3, aaddr); aaddr += 32;
    uint32_t b0,b1,b2,b3;
    ldsm4(b0,b1,b2,b3, bp0); bp0 += 32;
    mma16(acc[0], a0,a1,a2,a3, b0,b1);
    mma16(acc[1], a0,a1,a2,a3, b2,b3);
    ldsm4(b0,b1,b2,b3, bp1); bp1 += 32;
    mma16(acc[2], a0,a1,a2,a3, b0,b1);
    mma16(acc[3], a0,a1,a2,a3, b2,b3);
    ldsm4(b0,b1,b2,b3, bp2); bp2 += 32;
    mma16(acc[4], a0,a1,a2,a3, b0,b1);
    mma16(acc[5], a0,a1,a2,a3, b2,b3);
    ldsm4(b0,b1,b2,b3, bp3); bp3 += 32;
    mma16(acc[6], a0,a1,a2,a3, b0,b1);
    mma16(acc[7], a0,a1,a2,a3, b2,b3);
  }
}

// ---- prep kernel: W(f32,[k][n]) -> g_wt(f16,[f][n][k] half2-packed) ----
__global__ void prep_kernel(const float* __restrict__ W1,
                            const float* __restrict__ W2,
                            const float* __restrict__ Wr)
{
  for(int u = blockIdx.x*blockDim.x + threadIdx.x; u < NUNITS; u += gridDim.x*blockDim.x){
    float v0, v1;
    if(u < 262144){                       // W1: K=64
      int f = u >> 12, rem = u & 4095;
      int n = rem >> 5, kp = rem & 31;
      const float* s = W1 + (size_t)f*8192 + (kp*2)*128 + n;
      v0 = s[0]; v1 = s[128];
    } else if(u < 786432){                // W2: K=128
      int v = u - 262144;
      int f = v >> 13, rem = v & 8191;
      int n = rem >> 6, kp = rem & 63;
      const float* s = W2 + (size_t)f*16384 + (kp*2)*128 + n;
      v0 = s[0]; v1 = s[128];
    } else {                              // Wr: K=64
      int v = u - 786432;
      int f = v >> 12, rem = v & 4095;
      int n = rem >> 5, kp = rem & 31;
      const float* s = Wr + (size_t)f*8192 + (kp*2)*128 + n;
      v0 = s[0]; v1 = s[128];
    }
    g_wt[u] = pkh(v0, v1);
  }
}

// stage one K=64 tile (128 n-rows x 128B) at byte offset `dofs` in BB
__device__ __forceinline__ void stage_k64(uint32_t smu, uint32_t dofs,
                                          const __half* __restrict__ src, int tid){
#pragma unroll
  for(int i=0;i<4;++i){
    int id = tid + i*256;
    int n = id >> 3, c = id & 7;
    cpa16(smu + BB_B + dofs + (uint32_t)(n*144 + c*16), src + n*64 + c*8);
  }
}

__global__ void __launch_bounds__(NTH, 2)
nam_h2_kernel(const float* __restrict__ x,const float* __restrict__ centers,
              const float* __restrict__ logw,
              const float* __restrict__ b1,const float* __restrict__ g1,
              const float* __restrict__ be1,const float* __restrict__ b2,
              const float* __restrict__ g2,const float* __restrict__ be2,
              const float* __restrict__ br,
              const float* __restrict__ att,const float* __restrict__ bias,
              const float* __restrict__ Wpi,const float* __restrict__ bpi,
              const float* __restrict__ Wa,const float* __restrict__ ba,
              const float* __restrict__ Wb,const float* __restrict__ bb_,
              float* __restrict__ out)
{
  extern __shared__ char smc[];
  float* xt  = (float*)(smc + XT_B);
  float* pbf = (float*)(smc + PB_B);
  float2* lnb = (float2*)(smc + LNB_B);
  float* wfs = (float*)(smc + WFS_B);
  float* hb  = (float*)(smc + PB_B);      // reused after loop (4608B = PB+LNB)
  const uint32_t smu = s2u(smc);
  const __half* gw = (const __half*)g_wt;

  const int tid = threadIdx.x;
  const int w = tid >> 5, lane = tid & 31;
  const int g = lane >> 2, t = lane & 3;
  const int wr = w >> 1, wc = w & 1;
  const int rA0 = wr*16 + g;
  const int vbase = blockIdx.x * 64;

  // per-lane ldmatrix addresses
  const int arow = wr*16 + (lane&7) + ((lane>>3)&1)*8;
  const int akoff = (lane>>4)*16;
  const uint32_t aaddr_rbf = smu + RBF_B + arow*144 + akoff;
  const uint32_t aaddr_a1  = smu + A1_B  + arow*272 + akoff;
  const int brow = wc*64 + (lane>>4)*8 + (lane&7);
  const int bkoff = ((lane>>3)&1)*16;
  const uint32_t baddr_w1 = smu + BB_B + brow*144 + bkoff;
  const uint32_t baddr_wr = baddr_w1 + BBR_OFF;
  const uint32_t baddr_w2 = smu + BB_B + brow*272 + bkoff;

  // one-time: x tile + softmax(att) + prologue weight stage (W1,Wr of f=0)
#pragma unroll
  for(int i=0;i<16;++i){
    int id = tid + i*256;
    int r = id >> 6, ff = id & 63;
    xt[r*65 + ff] = clampf(x[(vbase + r)*64 + ff], -10.f, 10.f);
  }
  if(tid == 0){
    float mx = -3.4e38f;
    for(int i=0;i<64;++i) mx = fmaxf(mx, att[i]);
    float s = 0.f;
    for(int i=0;i<64;++i){ float e = expf(att[i]-mx); wfs[i] = e; s += e; }
    float inv = 1.f/s;
    for(int i=0;i<64;++i) wfs[i] *= inv;
  }
  stage_k64(smu, 0,       gw,           tid);            // W1(0)
  stage_k64(smu, BBR_OFF, gw + 1572864, tid);            // Wr(0)
  CPCOMMIT();
  __syncthreads();

  float agg[2][16];
#pragma unroll
  for(int r2=0;r2<2;++r2)
#pragma unroll
    for(int j=0;j<16;++j) agg[r2][j] = 0.f;

  for(int f=0; f<64; ++f){
    // ---- phase A: RBF(f) + params(f); W1/Wr(f) arriving (staged last phase E) ----
#pragma unroll
    for(int i=0;i<4;++i){
      int id = tid + i*256;
      int row = id >> 4, k4 = (id & 15) << 2;
      float xv = xt[row*65 + f];
      float4 ce = *(const float4*)&centers[f*64 + k4];
      float4 lw = *(const float4*)&logw[f*64 + k4];
      float o0,o1,o2,o3;
      { float wd=__expf(clampf(lw.x,-5.f,5.f))+0.1f; float d=clampf(__fdividef(xv-ce.x,wd),-10.f,10.f); o0=__expf(-0.5f*d*d); }
      { float wd=__expf(clampf(lw.y,-5.f,5.f))+0.1f; float d=clampf(__fdividef(xv-ce.y,wd),-10.f,10.f); o1=__expf(-0.5f*d*d); }
      { float wd=__expf(clampf(lw.z,-5.f,5.f))+0.1f; float d=clampf(__fdividef(xv-ce.z,wd),-10.f,10.f); o2=__expf(-0.5f*d*d); }
      { float wd=__expf(clampf(lw.w,-5.f,5.f))+0.1f; float d=clampf(__fdividef(xv-ce.w,wd),-10.f,10.f); o3=__expf(-0.5f*d*d); }
      uint2 u2; u2.x = pkh(o0,o1); u2.y = pkh(o2,o3);
      *(uint2*)(smc + RBF_B + row*144 + k4*2) = u2;
    }
    for(int i=tid; i<896; i+=256){
      int seg = i >> 7, c = i & 127;
      const float* sp = (seg==0)?b1:(seg==1)?g1:(seg==2)?be1:(seg==3)?b2:(seg==4)?g2:(seg==5)?be2:br;
      pbf[i] = sp[f*128 + c];
    }
    CPWAIT0();
    __syncthreads();                       // A end: rbf/pb/W1/Wr visible

    // ---- phase B: GEMMr (fold into agg) then GEMM1 + LN1 stats ----
    const float wf = wfs[f];
    {
      float accr[8][4];
#pragma unroll
      for(int j=0;j<8;++j){ accr[j][0]=accr[j][1]=accr[j][2]=accr[j][3]=0.f; }
      gemm_h<4>(accr, aaddr_rbf, baddr_wr, 144);
      const float cr = 0.1f*wf;
#pragma unroll
      for(int j=0;j<8;++j){
        int col = wc*64 + j*8 + t*2;
        float2 bv = *(const float2*)&pbf[768+col];
        agg[0][j*2]   += cr*(accr[j][0]+bv.x);
        agg[0][j*2+1] += cr*(accr[j][1]+bv.y);
        agg[1][j*2]   += cr*(accr[j][2]+bv.x);
        agg[1][j*2+1] += cr*(accr[j][3]+bv.y);
      }
    }
    float acc[8][4];
#pragma unroll
    for(int j=0;j<8;++j){ acc[j][0]=acc[j][1]=acc[j][2]=acc[j][3]=0.f; }
    gemm_h<4>(acc, aaddr_rbf, baddr_w1, 144);
    {
      float s0=0.f,q0=0.f,s1=0.f,q1=0.f;
#pragma unroll
      for(int j=0;j<8;++j){
        int col = wc*64 + j*8 + t*2;
        float2 bv = *(const float2*)&pbf[col];
        float v0=acc[j][0]+bv.x, v1=acc[j][1]+bv.y;
        float v2=acc[j][2]+bv.x, v3=acc[j][3]+bv.y;
        s0+=v0+v1; q0+=v0*v0+v1*v1;
        s1+=v2+v3; q1+=v2*v2+v3*v3;
      }
      s0=quad_sum(s0); q0=quad_sum(q0); s1=quad_sum(s1); q1=quad_sum(q1);
      if(t==0){
        lnb[rA0*2 + wc]     = make_float2(s0,q0);
        lnb[(rA0+8)*2 + wc] = make_float2(s1,q1);
      }
    }
    __syncthreads();                       // B end: BB reads done; lnb visible

    // ---- phase C: stage W2(f); epi1 (half2 GELU) -> a1 ----
    {
      const __half* src = gw + 524288 + (size_t)f*16384;
#pragma unroll
      for(int i=0;i<8;++i){
        int id = tid + i*256;
        int n = id >> 4, c = id & 15;
        cpa16(smu + BB_B + (uint32_t)(n*272 + c*16), src + n*128 + c*8);
      }
      CPCOMMIT();
    }
    {
      float2 pA0 = lnb[rA0*2 + wc],     pB0 = lnb[rA0*2 + (wc^1)];
      float2 pA1 = lnb[(rA0+8)*2 + wc], pB1 = lnb[(rA0+8)*2 + (wc^1)];
      float mu0=(pA0.x+pB0.x)*(1.f/128.f);
      float rs0=rsqrtf((pA0.y+pB0.y)*(1.f/128.f)-mu0*mu0+1e-5f);
      float mu1=(pA1.x+pB1.x)*(1.f/128.f);
      float rs1=rsqrtf((pA1.y+pB1.y)*(1.f/128.f)-mu1*mu1+1e-5f);
#pragma unroll
      for(int j=0;j<8;++j){
        int col = wc*64 + j*8 + t*2;
        float2 bv = *(const float2*)&pbf[col];
        float2 gv = *(const float2*)&pbf[128+col];
        float2 ev = *(const float2*)&pbf[256+col];
        float v0 = (acc[j][0]+bv.x-mu0)*rs0*gv.x+ev.x;
        float v1 = (acc[j][1]+bv.y-mu0)*rs0*gv.y+ev.y;
        float v2 = (acc[j][2]+bv.x-mu1)*rs1*gv.x+ev.x;
        float v3 = (acc[j][3]+bv.y-mu1)*rs1*gv.y+ev.y;
        *(uint32_t*)(smc + A1_B + rA0*272 + col*2)     = gelu_h2(pkh(v0,v1));
        *(uint32_t*)(smc + A1_B + (rA0+8)*272 + col*2) = gelu_h2(pkh(v2,v3));
      }
    }
    CPWAIT0();
    __syncthreads();                       // C end: bb=W2; a1 visible

    // ---- phase D: GEMM2 (K=128) + LN2 stats ----
    float acc2[8][4];
#pragma unroll
    for(int j=0;j<8;++j){ acc2[j][0]=acc2[j][1]=acc2[j][2]=acc2[j][3]=0.f; }
    gemm_h<8>(acc2, aaddr_a1, baddr_w2, 272);
    {
      float s0=0.f,q0=0.f,s1=0.f,q1=0.f;
#pragma unroll
      for(int j=0;j<8;++j){
        int col = wc*64 + j*8 + t*2;
        float2 bv = *(const float2*)&pbf[384+col];
        float v0=acc2[j][0]+bv.x, v1=acc2[j][1]+bv.y;
        float v2=acc2[j][2]+bv.x, v3=acc2[j][3]+bv.y;
        s0+=v0+v1; q0+=v0*v0+v1*v1;
        s1+=v2+v3; q1+=v2*v2+v3*v3;
      }
      s0=quad_sum(s0); q0=quad_sum(q0); s1=quad_sum(s1); q1=quad_sum(q1);
      if(t==0){
        lnb[rA0*2 + wc]     = make_float2(s0,q0);
        lnb[(rA0+8)*2 + wc] = make_float2(s1,q1);
      }
    }
    __syncthreads();                       // D end: W2/a1 reads done; lnb visible

    // ---- phase E: stage W1/Wr(f+1); epi2 -> agg ----
    {
      int fn = (f+1) & 63;
      stage_k64(smu, 0,       gw + (size_t)fn*8192,           tid);
      stage_k64(smu, BBR_OFF, gw + 1572864 + (size_t)fn*8192, tid);
      CPCOMMIT();
    }
    {
      float2 pA0 = lnb[rA0*2 + wc],     pB0 = lnb[rA0*2 + (wc^1)];
      float2 pA1 = lnb[(rA0+8)*2 + wc], pB1 = lnb[(rA0+8)*2 + (wc^1)];
      float mu0=(pA0.x+pB0.x)*(1.f/128.f);
      float rs0=rsqrtf((pA0.y+pB0.y)*(1.f/128.f)-mu0*mu0+1e-5f);
      float mu1=(pA1.x+pB1.x)*(1.f/128.f);
      float rs1=rsqrtf((pA1.y+pB1.y)*(1.f/128.f)-mu1*mu1+1e-5f);
#pragma unroll
      for(int j=0;j<8;++j){
        int col = wc*64 + j*8 + t*2;
        float2 bv = *(const float2*)&pbf[384+col];
        float2 gv = *(const float2*)&pbf[512+col];
        float2 ev = *(const float2*)&pbf[640+col];
        agg[0][j*2]   += wf*gelu_f((acc2[j][0]+bv.x-mu0)*rs0*gv.x+ev.x);
        agg[0][j*2+1] += wf*gelu_f((acc2[j][1]+bv.y-mu0)*rs0*gv.y+ev.y);
        agg[1][j*2]   += wf*gelu_f((acc2[j][2]+bv.x-mu1)*rs1*gv.x+ev.x);
        agg[1][j*2+1] += wf*gelu_f((acc2[j][3]+bv.y-mu1)*rs1*gv.y+ev.y);
      }
    }
    __syncthreads();                       // E end: pbf/lnb free for next A
  }

  // ---- mixture-beta head ----
  float p[2][9];
#pragma unroll
  for(int r2=0;r2<2;++r2)
#pragma unroll
    for(int q=0;q<9;++q) p[r2][q]=0.f;
#pragma unroll
  for(int j=0;j<8;++j){
#pragma unroll
    for(int cc=0;cc<2;++cc){
      int c = wc*64 + j*8 + t*2 + cc;
      float bs = __ldg(&bias[c]);
      float av0 = agg[0][j*2+cc] + bs;
      float av1 = agg[1][j*2+cc] + bs;
#pragma unroll
      for(int q=0;q<3;++q){
        float wp=__ldg(&Wpi[c*3+q]);
        float wa=__ldg(&Wa[c*3+q]);
        float wb=__ldg(&Wb[c*3+q]);
        p[0][q]+=av0*wp;   p[1][q]+=av1*wp;
        p[0][3+q]+=av0*wa; p[1][3+q]+=av1*wa;
        p[0][6+q]+=av0*wb; p[1][6+q]+=av1*wb;
      }
    }
  }
#pragma unroll
  for(int r2=0;r2<2;++r2)
#pragma unroll
    for(int q=0;q<9;++q) p[r2][q]=quad_sum(p[r2][q]);

  __syncthreads();
  if(t==0){
#pragma unroll
    for(int q=0;q<9;++q){
      hb[(wc*64 + rA0)*9 + q]     = p[0][q];
      hb[(wc*64 + rA0 + 8)*9 + q] = p[1][q];
    }
  }
  __syncthreads();

  if(wc==0 && t==0){
#pragma unroll
    for(int rr=0;rr<2;++rr){
      int r = rA0 + rr*8;
      float z[9];
#pragma unroll
      for(int q=0;q<9;++q) z[q] = hb[r*9+q] + hb[(64+r)*9+q];
      float p0=z[0]+bpi[0], p1=z[1]+bpi[1], p2=z[2]+bpi[2];
      float m=fmaxf(p0,fmaxf(p1,p2));
      float e0=expf(p0-m), e1=expf(p1-m), e2=expf(p2-m);
      float al0=clampf(softplus_f(z[3]+ba[0])+1.01f,1.01f,100.f);
      float al1=clampf(softplus_f(z[4]+ba[1])+1.01f,1.01f,100.f);
      float al2=clampf(softplus_f(z[5]+ba[2])+1.01f,1.01f,100.f);
      float bt0=clampf(softplus_f(z[6]+bb_[0])+1.01f,1.01f,100.f);
      float bt1=clampf(softplus_f(z[7]+bb_[1])+1.01f,1.01f,100.f);
      float bt2=clampf(softplus_f(z[8]+bb_[2])+1.01f,1.01f,100.f);
      float pred=e0*al0/(al0+bt0)+e1*al1/(al1+bt1)+e2*al2/(al2+bt2);
      pred/=(e0+e1+e2);
      out[vbase+r]=clampf(pred,0.001f,0.999f);
    }
  }
}

extern "C" void kernel_launch(void* const* d_in,const int* in_sizes,int n_in,
                              void* d_out,int out_size)
{
  const float* x=(const float*)d_in[0];
  const float* centers=(const float*)d_in[1];
  const float* logw=(const float*)d_in[2];
  const float* W1=(const float*)d_in[3];
  const float* b1=(const float*)d_in[4];
  const float* g1=(const float*)d_in[5];
  const float* be1=(const float*)d_in[6];
  const float* W2=(const float*)d_in[7];
  const float* b2=(const float*)d_in[8];
  const float* g2=(const float*)d_in[9];
  const float* be2=(const float*)d_in[10];
  const float* Wr=(const float*)d_in[11];
  const float* br=(const float*)d_in[12];
  const float* att=(const float*)d_in[13];
  const float* bias=(const float*)d_in[14];
  const float* Wpi=(const float*)d_in[15];
  const float* bpi=(const float*)d_in[16];
  const float* Wa=(const float*)d_in[17];
  const float* ba=(const float*)d_in[18];
  const float* Wb=(const float*)d_in[19];
  const float* bb=(const float*)d_in[20];
  float* out=(float*)d_out;

  prep_kernel<<<512, 256>>>(W1, W2, Wr);

  cudaFuncSetAttribute(nam_h2_kernel,cudaFuncAttributeMaxDynamicSharedMemorySize,SMEM_B);
  nam_h2_kernel<<<256,NTH,SMEM_B>>>(x,centers,logw,b1,g1,be1,b2,g2,be2,br,
                                    att,bias,Wpi,bpi,Wa,ba,Wb,bb,out);
}